// round 16
// baseline (speedup 1.0000x reference)
#include <cuda_runtime.h>
#include <cuda_fp16.h>
#include <cstdint>

#define NE   8
#define NH   1024
#define NM   2048
#define NTOK 2048
#define SLOT_CAP     6144
#define SHARED_HBASE 6144
#define HROWS        8192
#define MAX_TILES    48

// fp16 smem layouts (word = 4B = 2 fp16)
#define A_W    20
#define A_BUFW 2560    // 128 * 20
#define B_W    68
#define B_BUFW 2176    // 32 * 68
#define SW1    (A_BUFW + 2 * B_BUFW)
#define SW2    (A_BUFW + B_BUFW)
#define SMEM1_BYTES (4 * SW1 * 4)
#define SMEM2_BYTES (4 * SW2 * 4)

// ---------------- device scratch ----------------
__device__ int    g_rows[SLOT_CAP];
__device__ float  g_wts[SLOT_CAP];
__device__ int    g_tile_e[MAX_TILES];
__device__ int    g_tile_base[MAX_TILES];
__device__ int    g_num_tiles;
__device__ int    g_topk_idx[NTOK * 2];
__device__ float  g_topk_prob[NTOK * 2];
__device__ __half g_hbuf[(size_t)HROWS * NM];
__device__ __half g_xh[(size_t)NTOK * NH];
__device__ __half g_wgh[(size_t)NE * NH * NM];
__device__ __half g_wuh[(size_t)NE * NH * NM];
__device__ __half g_wdh[(size_t)NE * NM * NH];
__device__ __half g_sgh[(size_t)NH * NM];
__device__ __half g_suh[(size_t)NH * NM];
__device__ __half g_sdh[(size_t)NM * NH];

// ---------------- helpers ----------------
__device__ __forceinline__ uint32_t smem_u32(const void* p) {
    uint32_t a;
    asm("{ .reg .u64 t; cvta.to.shared.u64 t, %1; cvt.u32.u64 %0, t; }" : "=r"(a) : "l"(p));
    return a;
}
__device__ __forceinline__ uint32_t pack2(float lo, float hi) {
    __half2 h = __floats2half2_rn(lo, hi);
    return *(uint32_t*)&h;
}
__device__ __forceinline__ float silu_f(float v) { return v / (1.0f + __expf(-v)); }

__device__ __forceinline__ void cpa16(uint32_t dst, const void* src, int szbytes) {
    asm volatile("cp.async.cg.shared.global [%0], [%1], 16, %2;"
        :: "r"(dst), "l"(src), "r"(szbytes) : "memory");
}
#define CP_COMMIT() asm volatile("cp.async.commit_group;" ::: "memory")
#define CP_WAIT2()  asm volatile("cp.async.wait_group 2;" ::: "memory")

__device__ __forceinline__ void ldsm4(uint32_t* r, uint32_t addr) {
    asm volatile("ldmatrix.sync.aligned.m8n8.x4.shared.b16 {%0,%1,%2,%3}, [%4];"
        : "=r"(r[0]), "=r"(r[1]), "=r"(r[2]), "=r"(r[3]) : "r"(addr));
}
__device__ __forceinline__ void ldsm4t(uint32_t* r, uint32_t addr) {
    asm volatile("ldmatrix.sync.aligned.m8n8.x4.trans.shared.b16 {%0,%1,%2,%3}, [%4];"
        : "=r"(r[0]), "=r"(r[1]), "=r"(r[2]), "=r"(r[3]) : "r"(addr));
}
__device__ __forceinline__ void mma16(float* d, const uint32_t* a, uint32_t b0, uint32_t b1) {
    asm volatile(
        "mma.sync.aligned.m16n8k16.row.col.f32.f16.f16.f32 "
        "{%0,%1,%2,%3},{%4,%5,%6,%7},{%8,%9},{%0,%1,%2,%3};"
        : "+f"(d[0]), "+f"(d[1]), "+f"(d[2]), "+f"(d[3])
        : "r"(a[0]), "r"(a[1]), "r"(a[2]), "r"(a[3]), "r"(b0), "r"(b1));
}

// ---------------- fused fp32->fp16 convert of 3 tensors, 16 elems/thread ----------------
__global__ void cvt16x3(const float4* __restrict__ s0, const float4* __restrict__ s1,
                        const float4* __restrict__ s2,
                        uint4* __restrict__ d0, uint4* __restrict__ d1,
                        uint4* __restrict__ d2, int n16) {
    int i = blockIdx.x * blockDim.x + threadIdx.x;
    const float4* s;
    uint4* d;
    int k;
    if (i < n16)          { s = s0; d = d0; k = i; }
    else if (i < 2 * n16) { s = s1; d = d1; k = i - n16; }
    else if (i < 3 * n16) { s = s2; d = d2; k = i - 2 * n16; }
    else return;
    float4 a = s[4 * k], b = s[4 * k + 1], c = s[4 * k + 2], e = s[4 * k + 3];
    d[2 * k]     = make_uint4(pack2(a.x, a.y), pack2(a.z, a.w),
                              pack2(b.x, b.y), pack2(b.z, b.w));
    d[2 * k + 1] = make_uint4(pack2(c.x, c.y), pack2(c.z, c.w),
                              pack2(e.x, e.y), pack2(e.z, e.w));
}

// ---------------- routing (also emits fp16 x) ----------------
__global__ void moe_route(const float* __restrict__ x,
                          const float* __restrict__ gw,
                          const float* __restrict__ beta) {
    int b = blockIdx.x;
    const float* xr = x + (size_t)b * NH;
    float acc[NE];
#pragma unroll
    for (int e = 0; e < NE; e++) acc[e] = 0.f;
    for (int h = threadIdx.x; h < NH; h += 256) {
        float xv = xr[h];
        g_xh[(size_t)b * NH + h] = __float2half(xv);
#pragma unroll
        for (int e = 0; e < NE; e++) acc[e] += xv * gw[e * NH + h];
    }
#pragma unroll
    for (int off = 16; off > 0; off >>= 1)
#pragma unroll
        for (int e = 0; e < NE; e++)
            acc[e] += __shfl_down_sync(0xFFFFFFFFu, acc[e], off);
    __shared__ float part[8][NE];
    int lane = threadIdx.x & 31, warp = threadIdx.x >> 5;
    if (lane == 0)
#pragma unroll
        for (int e = 0; e < NE; e++) part[warp][e] = acc[e];
    __syncthreads();
    if (threadIdx.x == 0) {
        float lg[NE];
#pragma unroll
        for (int e = 0; e < NE; e++) {
            float s = 0.f;
#pragma unroll
            for (int w = 0; w < 8; w++) s += part[w][e];
            lg[e] = s;
        }
        int i1 = 0; float b1 = -1e30f;
#pragma unroll
        for (int e = 0; e < NE; e++) {
            float v = lg[e] + beta[e];
            if (v > b1) { b1 = v; i1 = e; }
        }
        int i2 = -1; float b2 = -1e30f;
#pragma unroll
        for (int e = 0; e < NE; e++) {
            if (e == i1) continue;
            float v = lg[e] + beta[e];
            if (v > b2) { b2 = v; i2 = e; }
        }
        g_topk_idx[2 * b + 0] = i1;
        g_topk_prob[2 * b + 0] = 1.f / (1.f + __expf(-lg[i1]));
        g_topk_idx[2 * b + 1] = i2;
        g_topk_prob[2 * b + 1] = 1.f / (1.f + __expf(-lg[i2]));
    }
}

// ---------------- build: warp-aggregated counting + scatter ----------------
__global__ void moe_build() {
    __shared__ int wcnt[16][NE];
    __shared__ int seg[NE], fill[NE];
    const int tid = threadIdx.x, lane = tid & 31, w = tid >> 5;
    for (int i = tid; i < SLOT_CAP; i += 512) g_rows[i] = -1;
    if (lane < NE) wcnt[w][lane] = 0;
    if (tid < NE) fill[tid] = 0;
    __syncthreads();

    int e_loc[8];
#pragma unroll
    for (int it = 0; it < 8; it++) {
        int i = tid + 512 * it;
        int e = g_topk_idx[i];
        e_loc[it] = e;
#pragma unroll
        for (int ee = 0; ee < NE; ee++) {
            unsigned m = __ballot_sync(0xFFFFFFFFu, e == ee);
            if (lane == 0) wcnt[w][ee] += __popc(m);
        }
    }
    __syncthreads();
    if (tid == 0) {
        int off = 0, nt = 0;
        for (int e = 0; e < NE; e++) {
            int c = 0;
            for (int ww = 0; ww < 16; ww++) c += wcnt[ww][e];
            seg[e] = off;
            int tiles = (c + 127) >> 7;
            for (int t = 0; t < tiles; t++) {
                g_tile_e[nt] = e;
                g_tile_base[nt] = off + (t << 7);
                nt++;
            }
            off += tiles << 7;
        }
        g_num_tiles = nt;
    }
    __syncthreads();
#pragma unroll
    for (int it = 0; it < 8; it++) {
        int i = tid + 512 * it;
        int e = e_loc[it];
#pragma unroll
        for (int ee = 0; ee < NE; ee++) {
            unsigned m = __ballot_sync(0xFFFFFFFFu, e == ee);
            if (!m) continue;                       // uniform across warp
            int leader = __ffs(m) - 1;
            int base = 0;
            if (lane == leader) base = atomicAdd(&fill[ee], __popc(m));
            base = __shfl_sync(0xFFFFFFFFu, base, leader);
            if (e == ee) {
                int p = seg[ee] + base + __popc(m & ((1u << lane) - 1u));
                g_rows[p] = i >> 1;
                g_wts[p]  = g_topk_prob[i];
            }
        }
    }
}

// ---------------- GEMM1: h = silu(x@Wg)*(x@Wu), CTA 128m x 128n, 512 thr ----------------
template <bool SHARED>
__global__ void __launch_bounds__(512)
moe_gemm1_mma(const __half* __restrict__ xh,
              const __half* __restrict__ Wg,
              const __half* __restrict__ Wu) {
    extern __shared__ uint32_t smw[];
    int by = blockIdx.y, e, base;
    if (SHARED) { e = 0; base = by * 128; }
    else {
        if (by >= g_num_tiles) return;
        e = g_tile_e[by];
        base = g_tile_base[by];
    }
    const int m0 = blockIdx.x * 128;
    const __half* wg = Wg + (size_t)e * NH * NM;
    const __half* wu = Wu + (size_t)e * NH * NM;

    const uint32_t sbase = smem_u32(smw);
    const int tid = threadIdx.x;
    const int lane = tid & 31, wid = tid >> 5;
    const int j = lane & 3, g = lane >> 2;
    const int wm = (wid & 3) * 32, wn = (wid >> 2) * 32;

    const int a_row  = wm + ((lane >> 3) & 1) * 8 + (lane & 7);
    const int a_coff = (lane >> 4) * 4;
    const int b_krow = ((lane >> 3) & 1) * 8 + (lane & 7);
    const int b_coff = (wn >> 1) + (lane >> 4) * 4;

    const int row_a = tid & 127, qa = tid >> 7;
    int tok = SHARED ? (base + row_a) : g_rows[base + row_a];
    const bool okA = (tok >= 0);
    const int a_sz = okA ? 16 : 0;
    const __half* ax = xh + (size_t)(okA ? tok : 0) * NH + 8 * qa;
    const int bkk = tid >> 4, bc = tid & 15;
    const uint32_t a_dst = sbase + (row_a * A_W + 4 * qa) * 4;
    const uint32_t bg_dst = sbase + (A_BUFW + bkk * B_W + 4 * bc) * 4;
    const uint32_t bu_dst = bg_dst + B_BUFW * 4;
    const __half* wgp = wg + (size_t)bkk * NM + m0 + 8 * bc;
    const __half* wup = wu + (size_t)bkk * NM + m0 + 8 * bc;

    float dg[2][4][4], du[2][4][4];
#pragma unroll
    for (int a1 = 0; a1 < 2; a1++)
#pragma unroll
        for (int b1 = 0; b1 < 4; b1++)
#pragma unroll
            for (int c1 = 0; c1 < 4; c1++) { dg[a1][b1][c1] = 0.f; du[a1][b1][c1] = 0.f; }

    const int KC = NH / 32;
#pragma unroll
    for (int s = 0; s < 3; s++) {
        uint32_t so = s * SW1 * 4;
        cpa16(a_dst + so, ax + s * 32, a_sz);
        cpa16(bg_dst + so, wgp + (size_t)s * 32 * NM, 16);
        cpa16(bu_dst + so, wup + (size_t)s * 32 * NM, 16);
        CP_COMMIT();
    }

    for (int kc = 0; kc < KC; kc++) {
        CP_WAIT2();
        __syncthreads();
        const int st = kc & 3;
        const uint32_t asb = sbase + (st * SW1) * 4;
        const uint32_t bgb = asb + A_BUFW * 4;
        const uint32_t bub = bgb + B_BUFW * 4;
#pragma unroll
        for (int ks = 0; ks < 2; ks++) {
            uint32_t a[2][4];
#pragma unroll
            for (int mi = 0; mi < 2; mi++)
                ldsm4(a[mi], asb + ((a_row + mi * 16) * A_W + ks * 8 + a_coff) * 4);
            uint32_t fg[2][4], fu[2][4];
#pragma unroll
            for (int nip = 0; nip < 2; nip++) {
                uint32_t boff = ((b_krow + ks * 16) * B_W + b_coff + nip * 8) * 4;
                ldsm4t(fg[nip], bgb + boff);
                ldsm4t(fu[nip], bub + boff);
            }
#pragma unroll
            for (int ni = 0; ni < 4; ni++) {
                int nip = ni >> 1, o = (ni & 1) * 2;
#pragma unroll
                for (int mi = 0; mi < 2; mi++) {
                    mma16(dg[mi][ni], a[mi], fg[nip][o], fg[nip][o + 1]);
                    mma16(du[mi][ni], a[mi], fu[nip][o], fu[nip][o + 1]);
                }
            }
        }
        int nk = kc + 3;
        if (nk < KC) {
            uint32_t so = (nk & 3) * SW1 * 4;
            cpa16(a_dst + so, ax + nk * 32, a_sz);
            cpa16(bg_dst + so, wgp + (size_t)nk * 32 * NM, 16);
            cpa16(bu_dst + so, wup + (size_t)nk * 32 * NM, 16);
        }
        CP_COMMIT();
    }

    const int hb = (SHARED ? SHARED_HBASE : 0) + base;
    uint32_t* h32 = (uint32_t*)g_hbuf;
#pragma unroll
    for (int mi = 0; mi < 2; mi++)
#pragma unroll
        for (int ni = 0; ni < 4; ni++) {
            int r = hb + wm + 16 * mi + g;
            int cw = (m0 + wn + 8 * ni + 2 * j) >> 1;
            h32[(size_t)r * (NM / 2) + cw] =
                pack2(silu_f(dg[mi][ni][0]) * du[mi][ni][0],
                      silu_f(dg[mi][ni][1]) * du[mi][ni][1]);
            h32[(size_t)(r + 8) * (NM / 2) + cw] =
                pack2(silu_f(dg[mi][ni][2]) * du[mi][ni][2],
                      silu_f(dg[mi][ni][3]) * du[mi][ni][3]);
        }
}

// ---------------- GEMM2: out += h @ Wd, CTA 128m x 128n, 256 thr, warp 32m x 64n ----------
template <bool SHARED>
__global__ void __launch_bounds__(256, 2)
moe_gemm2_mma(const __half* __restrict__ Wd, float* __restrict__ out) {
    extern __shared__ uint32_t smw[];
    int by = blockIdx.y, e, base;
    if (SHARED) { e = 0; base = by * 128; }
    else {
        if (by >= g_num_tiles) return;
        e = g_tile_e[by];
        base = g_tile_base[by];
    }
    const int n0 = blockIdx.x * 128;
    const __half* wd = Wd + (size_t)e * NM * NH;
    const int hb = (SHARED ? SHARED_HBASE : 0) + base;

    const uint32_t sbase = smem_u32(smw);
    const int tid = threadIdx.x;
    const int lane = tid & 31, wid = tid >> 5;
    const int j = lane & 3, g = lane >> 2;
    const int wm = (wid & 3) * 32, wn = (wid >> 2) * 64;

    const int a_row  = wm + ((lane >> 3) & 1) * 8 + (lane & 7);
    const int a_coff = (lane >> 4) * 4;
    const int b_krow = ((lane >> 3) & 1) * 8 + (lane & 7);
    const int b_coff = (wn >> 1) + (lane >> 4) * 4;

    const int row_a = tid & 127, qa0 = (tid >> 7) * 2;
    const __half* ax = g_hbuf + (size_t)(hb + row_a) * NM + 8 * qa0;
    const int bkk = tid >> 3, bc0 = (tid & 7) * 2;
    const uint32_t a_dst = sbase + (row_a * A_W + 4 * qa0) * 4;
    const uint32_t b_dst = sbase + (A_BUFW + bkk * B_W + 4 * bc0) * 4;
    const __half* wdp = wd + (size_t)bkk * NH + n0 + 8 * bc0;

    float d[2][8][4];
#pragma unroll
    for (int a1 = 0; a1 < 2; a1++)
#pragma unroll
        for (int b1 = 0; b1 < 8; b1++)
#pragma unroll
            for (int c1 = 0; c1 < 4; c1++) d[a1][b1][c1] = 0.f;

    const int KC = NM / 32;
#pragma unroll
    for (int s = 0; s < 3; s++) {
        uint32_t so = s * SW2 * 4;
        cpa16(a_dst + so, ax + s * 32, 16);
        cpa16(a_dst + so + 16, ax + s * 32 + 8, 16);
        cpa16(b_dst + so, wdp + (size_t)s * 32 * NH, 16);
        cpa16(b_dst + so + 16, wdp + (size_t)s * 32 * NH + 8, 16);
        CP_COMMIT();
    }

    for (int kc = 0; kc < KC; kc++) {
        CP_WAIT2();
        __syncthreads();
        const int st = kc & 3;
        const uint32_t asb = sbase + (st * SW2) * 4;
        const uint32_t bsb = asb + A_BUFW * 4;
#pragma unroll
        for (int ks = 0; ks < 2; ks++) {
            uint32_t a[2][4];
#pragma unroll
            for (int mi = 0; mi < 2; mi++)
                ldsm4(a[mi], asb + ((a_row + mi * 16) * A_W + ks * 8 + a_coff) * 4);
            uint32_t fb[4][4];
#pragma unroll
            for (int nip = 0; nip < 4; nip++)
                ldsm4t(fb[nip], bsb + ((b_krow + ks * 16) * B_W + b_coff + nip * 8) * 4);
#pragma unroll
            for (int ni = 0; ni < 8; ni++) {
                int nip = ni >> 1, o = (ni & 1) * 2;
#pragma unroll
                for (int mi = 0; mi < 2; mi++)
                    mma16(d[mi][ni], a[mi], fb[nip][o], fb[nip][o + 1]);
            }
        }
        int nk = kc + 3;
        if (nk < KC) {
            uint32_t so = (nk & 3) * SW2 * 4;
            cpa16(a_dst + so, ax + nk * 32, 16);
            cpa16(a_dst + so + 16, ax + nk * 32 + 8, 16);
            cpa16(b_dst + so, wdp + (size_t)nk * 32 * NH, 16);
            cpa16(b_dst + so + 16, wdp + (size_t)nk * 32 * NH + 8, 16);
        }
        CP_COMMIT();
    }

    if (SHARED) {
#pragma unroll
        for (int mi = 0; mi < 2; mi++)
#pragma unroll
            for (int ni = 0; ni < 8; ni++) {
                int r = base + wm + 16 * mi + g;
                int col = n0 + wn + 8 * ni + 2 * j;
                *(float2*)(out + (size_t)r * NH + col) =
                    make_float2(d[mi][ni][0], d[mi][ni][1]);
                *(float2*)(out + (size_t)(r + 8) * NH + col) =
                    make_float2(d[mi][ni][2], d[mi][ni][3]);
            }
    } else {
#pragma unroll
        for (int mi = 0; mi < 2; mi++) {
            int s0 = base + wm + 16 * mi + g;
            int t0 = g_rows[s0], t1 = g_rows[s0 + 8];
            float w0 = g_wts[s0], w1 = g_wts[s0 + 8];
#pragma unroll
            for (int ni = 0; ni < 8; ni++) {
                int col = n0 + wn + 8 * ni + 2 * j;
                if (t0 >= 0) {
                    atomicAdd(out + (size_t)t0 * NH + col,     w0 * d[mi][ni][0]);
                    atomicAdd(out + (size_t)t0 * NH + col + 1, w0 * d[mi][ni][1]);
                }
                if (t1 >= 0) {
                    atomicAdd(out + (size_t)t1 * NH + col,     w1 * d[mi][ni][2]);
                    atomicAdd(out + (size_t)t1 * NH + col + 1, w1 * d[mi][ni][3]);
                }
            }
        }
    }
}

// ---------------- launch ----------------
extern "C" void kernel_launch(void* const* d_in, const int* in_sizes, int n_in,
                              void* d_out, int out_size) {
    const float* x    = (const float*)d_in[0];
    const float* gw   = (const float*)d_in[1];
    const float* beta = (const float*)d_in[2];
    const float* gpw  = (const float*)d_in[3];
    const float* upw  = (const float*)d_in[4];
    const float* dpw  = (const float*)d_in[5];
    const float* sgw  = (const float*)d_in[6];
    const float* suw  = (const float*)d_in[7];
    const float* sdw  = (const float*)d_in[8];
    float* out = (float*)d_out;

    static __half *wgh = nullptr, *wuh = nullptr, *wdh = nullptr,
                  *sgh = nullptr, *suh = nullptr, *sdh = nullptr, *xh = nullptr;
    static cudaStream_t s1 = nullptr;
    static cudaEvent_t ev_fork = nullptr, ev_build = nullptr, ev_g1r = nullptr;
    if (!wgh) {
        void* p;
        cudaGetSymbolAddress(&p, g_wgh); wgh = (__half*)p;
        cudaGetSymbolAddress(&p, g_wuh); wuh = (__half*)p;
        cudaGetSymbolAddress(&p, g_wdh); wdh = (__half*)p;
        cudaGetSymbolAddress(&p, g_sgh); sgh = (__half*)p;
        cudaGetSymbolAddress(&p, g_suh); suh = (__half*)p;
        cudaGetSymbolAddress(&p, g_sdh); sdh = (__half*)p;
        cudaGetSymbolAddress(&p, g_xh);  xh  = (__half*)p;
        cudaFuncSetAttribute(moe_gemm1_mma<false>, cudaFuncAttributeMaxDynamicSharedMemorySize, SMEM1_BYTES);
        cudaFuncSetAttribute(moe_gemm1_mma<true>,  cudaFuncAttributeMaxDynamicSharedMemorySize, SMEM1_BYTES);
        cudaFuncSetAttribute(moe_gemm2_mma<false>, cudaFuncAttributeMaxDynamicSharedMemorySize, SMEM2_BYTES);
        cudaFuncSetAttribute(moe_gemm2_mma<true>,  cudaFuncAttributeMaxDynamicSharedMemorySize, SMEM2_BYTES);
        cudaStreamCreateWithFlags(&s1, cudaStreamNonBlocking);
        cudaEventCreateWithFlags(&ev_fork, cudaEventDisableTiming);
        cudaEventCreateWithFlags(&ev_build, cudaEventDisableTiming);
        cudaEventCreateWithFlags(&ev_g1r, cudaEventDisableTiming);
    }

    const int NBIG16 = NE * NH * NM / 16;
    const int NSML16 = NH * NM / 16;

    // Fork: big expert-weight conversions on side stream s1.
    cudaEventRecord(ev_fork, 0);
    cudaStreamWaitEvent(s1, ev_fork, 0);
    cvt16x3<<<(3 * NBIG16 + 255) / 256, 256, 0, s1>>>(
        (const float4*)gpw, (const float4*)upw, (const float4*)dpw,
        (uint4*)wgh, (uint4*)wuh, (uint4*)wdh, NBIG16);

    // Main stream: small cvt + routing + build.
    cvt16x3<<<(3 * NSML16 + 255) / 256, 256>>>(
        (const float4*)sgw, (const float4*)suw, (const float4*)sdw,
        (uint4*)sgh, (uint4*)suh, (uint4*)sdh, NSML16);
    moe_route<<<NTOK, 256>>>(x, gw, beta);
    moe_build<<<1, 512>>>();
    cudaEventRecord(ev_build, 0);

    // Side stream: routed gemm1 (needs big cvt [in-stream] + build/xh [event]).
    cudaStreamWaitEvent(s1, ev_build, 0);
    moe_gemm1_mma<false><<<dim3(NM / 128, 40), 512, SMEM1_BYTES, s1>>>(xh, wgh, wuh);
    cudaEventRecord(ev_g1r, s1);

    // Main stream: shared-expert chain (out initialized by shared gemm2).
    moe_gemm1_mma<true><<<dim3(NM / 128, NTOK / 128), 512, SMEM1_BYTES>>>(xh, sgh, suh);
    moe_gemm2_mma<true><<<dim3(NH / 128, NTOK / 128), 256, SMEM2_BYTES>>>(sdh, out);

    // Join: routed gemm2 needs routed h + initialized out.
    cudaStreamWaitEvent(0, ev_g1r, 0);
    moe_gemm2_mma<false><<<dim3(NH / 128, 40), 256, SMEM2_BYTES>>>(wdh, out);
}

// round 17
// speedup vs baseline: 1.0370x; 1.0370x over previous
#include <cuda_runtime.h>
#include <cuda_fp16.h>
#include <cstdint>

#define NE   8
#define NH   1024
#define NM   2048
#define NTOK 2048
#define SLOT_CAP     6144
#define SHARED_HBASE 6144
#define HROWS        8192
#define MAX_TILES    48

// fp16 smem layouts (word = 4B = 2 fp16)
#define A_W    20
#define A_BUFW 2560    // 128 * 20
#define B_W    68
#define B_BUFW 2176    // 32 * 68
#define SW1    (A_BUFW + 2 * B_BUFW)
#define SW2    (A_BUFW + B_BUFW)
#define SMEM1_BYTES (4 * SW1 * 4)
#define SMEM2_BYTES (4 * SW2 * 4)

// ---------------- device scratch ----------------
__device__ int    g_rows[SLOT_CAP];
__device__ float  g_wts[SLOT_CAP];
__device__ int    g_tile_e[MAX_TILES];
__device__ int    g_tile_base[MAX_TILES];
__device__ int    g_num_tiles;
__device__ int    g_topk_idx[NTOK * 2];
__device__ float  g_topk_prob[NTOK * 2];
__device__ __half g_hbuf[(size_t)HROWS * NM];
__device__ __half g_xh[(size_t)NTOK * NH];
__device__ __half g_wgh[(size_t)NE * NH * NM];
__device__ __half g_wuh[(size_t)NE * NH * NM];
__device__ __half g_wdh[(size_t)NE * NM * NH];
__device__ __half g_sgh[(size_t)NH * NM];
__device__ __half g_suh[(size_t)NH * NM];
__device__ __half g_sdh[(size_t)NM * NH];

// ---------------- helpers ----------------
__device__ __forceinline__ uint32_t smem_u32(const void* p) {
    uint32_t a;
    asm("{ .reg .u64 t; cvta.to.shared.u64 t, %1; cvt.u32.u64 %0, t; }" : "=r"(a) : "l"(p));
    return a;
}
__device__ __forceinline__ uint32_t pack2(float lo, float hi) {
    __half2 h = __floats2half2_rn(lo, hi);
    return *(uint32_t*)&h;
}
__device__ __forceinline__ float silu_f(float v) { return v / (1.0f + __expf(-v)); }

__device__ __forceinline__ void cpa16(uint32_t dst, const void* src, int szbytes) {
    asm volatile("cp.async.cg.shared.global [%0], [%1], 16, %2;"
        :: "r"(dst), "l"(src), "r"(szbytes) : "memory");
}
#define CP_COMMIT() asm volatile("cp.async.commit_group;" ::: "memory")
#define CP_WAIT2()  asm volatile("cp.async.wait_group 2;" ::: "memory")

__device__ __forceinline__ void ldsm4(uint32_t* r, uint32_t addr) {
    asm volatile("ldmatrix.sync.aligned.m8n8.x4.shared.b16 {%0,%1,%2,%3}, [%4];"
        : "=r"(r[0]), "=r"(r[1]), "=r"(r[2]), "=r"(r[3]) : "r"(addr));
}
__device__ __forceinline__ void ldsm4t(uint32_t* r, uint32_t addr) {
    asm volatile("ldmatrix.sync.aligned.m8n8.x4.trans.shared.b16 {%0,%1,%2,%3}, [%4];"
        : "=r"(r[0]), "=r"(r[1]), "=r"(r[2]), "=r"(r[3]) : "r"(addr));
}
__device__ __forceinline__ void mma16(float* d, const uint32_t* a, uint32_t b0, uint32_t b1) {
    asm volatile(
        "mma.sync.aligned.m16n8k16.row.col.f32.f16.f16.f32 "
        "{%0,%1,%2,%3},{%4,%5,%6,%7},{%8,%9},{%0,%1,%2,%3};"
        : "+f"(d[0]), "+f"(d[1]), "+f"(d[2]), "+f"(d[3])
        : "r"(a[0]), "r"(a[1]), "r"(a[2]), "r"(a[3]), "r"(b0), "r"(b1));
}

// ---------------- fused fp32->fp16 convert of 3 tensors, 16 elems/thread ----------------
__global__ void cvt16x3(const float4* __restrict__ s0, const float4* __restrict__ s1,
                        const float4* __restrict__ s2,
                        uint4* __restrict__ d0, uint4* __restrict__ d1,
                        uint4* __restrict__ d2, int n16) {
    int i = blockIdx.x * blockDim.x + threadIdx.x;
    const float4* s;
    uint4* d;
    int k;
    if (i < n16)          { s = s0; d = d0; k = i; }
    else if (i < 2 * n16) { s = s1; d = d1; k = i - n16; }
    else if (i < 3 * n16) { s = s2; d = d2; k = i - 2 * n16; }
    else return;
    float4 a = s[4 * k], b = s[4 * k + 1], c = s[4 * k + 2], e = s[4 * k + 3];
    d[2 * k]     = make_uint4(pack2(a.x, a.y), pack2(a.z, a.w),
                              pack2(b.x, b.y), pack2(b.z, b.w));
    d[2 * k + 1] = make_uint4(pack2(c.x, c.y), pack2(c.z, c.w),
                              pack2(e.x, e.y), pack2(e.z, e.w));
}

// ---------------- routing (also emits fp16 x) ----------------
__global__ void moe_route(const float* __restrict__ x,
                          const float* __restrict__ gw,
                          const float* __restrict__ beta) {
    int b = blockIdx.x;
    const float* xr = x + (size_t)b * NH;
    float acc[NE];
#pragma unroll
    for (int e = 0; e < NE; e++) acc[e] = 0.f;
    for (int h = threadIdx.x; h < NH; h += 256) {
        float xv = xr[h];
        g_xh[(size_t)b * NH + h] = __float2half(xv);
#pragma unroll
        for (int e = 0; e < NE; e++) acc[e] += xv * gw[e * NH + h];
    }
#pragma unroll
    for (int off = 16; off > 0; off >>= 1)
#pragma unroll
        for (int e = 0; e < NE; e++)
            acc[e] += __shfl_down_sync(0xFFFFFFFFu, acc[e], off);
    __shared__ float part[8][NE];
    int lane = threadIdx.x & 31, warp = threadIdx.x >> 5;
    if (lane == 0)
#pragma unroll
        for (int e = 0; e < NE; e++) part[warp][e] = acc[e];
    __syncthreads();
    if (threadIdx.x == 0) {
        float lg[NE];
#pragma unroll
        for (int e = 0; e < NE; e++) {
            float s = 0.f;
#pragma unroll
            for (int w = 0; w < 8; w++) s += part[w][e];
            lg[e] = s;
        }
        int i1 = 0; float b1 = -1e30f;
#pragma unroll
        for (int e = 0; e < NE; e++) {
            float v = lg[e] + beta[e];
            if (v > b1) { b1 = v; i1 = e; }
        }
        int i2 = -1; float b2 = -1e30f;
#pragma unroll
        for (int e = 0; e < NE; e++) {
            if (e == i1) continue;
            float v = lg[e] + beta[e];
            if (v > b2) { b2 = v; i2 = e; }
        }
        g_topk_idx[2 * b + 0] = i1;
        g_topk_prob[2 * b + 0] = 1.f / (1.f + __expf(-lg[i1]));
        g_topk_idx[2 * b + 1] = i2;
        g_topk_prob[2 * b + 1] = 1.f / (1.f + __expf(-lg[i2]));
    }
}

// ---------------- build: match_any-aggregated counting + scatter ----------------
__global__ void moe_build() {
    __shared__ int cnt[NE], seg[NE], fill[NE];
    const int tid = threadIdx.x, lane = tid & 31;
    for (int i = tid; i < SLOT_CAP; i += 512) g_rows[i] = -1;
    if (tid < NE) { cnt[tid] = 0; fill[tid] = 0; }
    __syncthreads();

    int e_loc[8];
#pragma unroll
    for (int it = 0; it < 8; it++) {
        int i = tid + 512 * it;
        int e = g_topk_idx[i];
        e_loc[it] = e;
        unsigned m = __match_any_sync(0xFFFFFFFFu, e);
        int leader = __ffs(m) - 1;
        if (lane == leader) atomicAdd(&cnt[e], __popc(m));
    }
    __syncthreads();
    if (tid == 0) {
        int off = 0, nt = 0;
        for (int e = 0; e < NE; e++) {
            seg[e] = off;
            int tiles = (cnt[e] + 127) >> 7;
            for (int t = 0; t < tiles; t++) {
                g_tile_e[nt] = e;
                g_tile_base[nt] = off + (t << 7);
                nt++;
            }
            off += tiles << 7;
        }
        g_num_tiles = nt;
    }
    __syncthreads();
#pragma unroll
    for (int it = 0; it < 8; it++) {
        int i = tid + 512 * it;
        int e = e_loc[it];
        unsigned m = __match_any_sync(0xFFFFFFFFu, e);
        int leader = __ffs(m) - 1;
        int base = 0;
        if (lane == leader) base = atomicAdd(&fill[e], __popc(m));
        base = __shfl_sync(0xFFFFFFFFu, base, leader);
        int p = seg[e] + base + __popc(m & ((1u << lane) - 1u));
        g_rows[p] = i >> 1;
        g_wts[p]  = g_topk_prob[i];
    }
}

// ---------------- GEMM1: h = silu(x@Wg)*(x@Wu), CTA 128m x 128n, 512 thr ----------------
template <bool SHARED>
__global__ void __launch_bounds__(512)
moe_gemm1_mma(const __half* __restrict__ xh,
              const __half* __restrict__ Wg,
              const __half* __restrict__ Wu) {
    extern __shared__ uint32_t smw[];
    int by = blockIdx.y, e, base;
    if (SHARED) { e = 0; base = by * 128; }
    else {
        if (by >= g_num_tiles) return;
        e = g_tile_e[by];
        base = g_tile_base[by];
    }
    const int m0 = blockIdx.x * 128;
    const __half* wg = Wg + (size_t)e * NH * NM;
    const __half* wu = Wu + (size_t)e * NH * NM;

    const uint32_t sbase = smem_u32(smw);
    const int tid = threadIdx.x;
    const int lane = tid & 31, wid = tid >> 5;
    const int j = lane & 3, g = lane >> 2;
    const int wm = (wid & 3) * 32, wn = (wid >> 2) * 32;

    const int a_row  = wm + ((lane >> 3) & 1) * 8 + (lane & 7);
    const int a_coff = (lane >> 4) * 4;
    const int b_krow = ((lane >> 3) & 1) * 8 + (lane & 7);
    const int b_coff = (wn >> 1) + (lane >> 4) * 4;

    const int row_a = tid & 127, qa = tid >> 7;
    int tok = SHARED ? (base + row_a) : g_rows[base + row_a];
    const bool okA = (tok >= 0);
    const int a_sz = okA ? 16 : 0;
    const __half* ax = xh + (size_t)(okA ? tok : 0) * NH + 8 * qa;
    const int bkk = tid >> 4, bc = tid & 15;
    const uint32_t a_dst = sbase + (row_a * A_W + 4 * qa) * 4;
    const uint32_t bg_dst = sbase + (A_BUFW + bkk * B_W + 4 * bc) * 4;
    const uint32_t bu_dst = bg_dst + B_BUFW * 4;
    const __half* wgp = wg + (size_t)bkk * NM + m0 + 8 * bc;
    const __half* wup = wu + (size_t)bkk * NM + m0 + 8 * bc;

    float dg[2][4][4], du[2][4][4];
#pragma unroll
    for (int a1 = 0; a1 < 2; a1++)
#pragma unroll
        for (int b1 = 0; b1 < 4; b1++)
#pragma unroll
            for (int c1 = 0; c1 < 4; c1++) { dg[a1][b1][c1] = 0.f; du[a1][b1][c1] = 0.f; }

    const int KC = NH / 32;
#pragma unroll
    for (int s = 0; s < 3; s++) {
        uint32_t so = s * SW1 * 4;
        cpa16(a_dst + so, ax + s * 32, a_sz);
        cpa16(bg_dst + so, wgp + (size_t)s * 32 * NM, 16);
        cpa16(bu_dst + so, wup + (size_t)s * 32 * NM, 16);
        CP_COMMIT();
    }

    for (int kc = 0; kc < KC; kc++) {
        CP_WAIT2();
        __syncthreads();
        const int st = kc & 3;
        const uint32_t asb = sbase + (st * SW1) * 4;
        const uint32_t bgb = asb + A_BUFW * 4;
        const uint32_t bub = bgb + B_BUFW * 4;
#pragma unroll
        for (int ks = 0; ks < 2; ks++) {
            uint32_t a[2][4];
#pragma unroll
            for (int mi = 0; mi < 2; mi++)
                ldsm4(a[mi], asb + ((a_row + mi * 16) * A_W + ks * 8 + a_coff) * 4);
            uint32_t fg[2][4], fu[2][4];
#pragma unroll
            for (int nip = 0; nip < 2; nip++) {
                uint32_t boff = ((b_krow + ks * 16) * B_W + b_coff + nip * 8) * 4;
                ldsm4t(fg[nip], bgb + boff);
                ldsm4t(fu[nip], bub + boff);
            }
#pragma unroll
            for (int ni = 0; ni < 4; ni++) {
                int nip = ni >> 1, o = (ni & 1) * 2;
#pragma unroll
                for (int mi = 0; mi < 2; mi++) {
                    mma16(dg[mi][ni], a[mi], fg[nip][o], fg[nip][o + 1]);
                    mma16(du[mi][ni], a[mi], fu[nip][o], fu[nip][o + 1]);
                }
            }
        }
        int nk = kc + 3;
        if (nk < KC) {
            uint32_t so = (nk & 3) * SW1 * 4;
            cpa16(a_dst + so, ax + nk * 32, a_sz);
            cpa16(bg_dst + so, wgp + (size_t)nk * 32 * NM, 16);
            cpa16(bu_dst + so, wup + (size_t)nk * 32 * NM, 16);
        }
        CP_COMMIT();
    }

    const int hb = (SHARED ? SHARED_HBASE : 0) + base;
    uint32_t* h32 = (uint32_t*)g_hbuf;
#pragma unroll
    for (int mi = 0; mi < 2; mi++)
#pragma unroll
        for (int ni = 0; ni < 4; ni++) {
            int r = hb + wm + 16 * mi + g;
            int cw = (m0 + wn + 8 * ni + 2 * j) >> 1;
            h32[(size_t)r * (NM / 2) + cw] =
                pack2(silu_f(dg[mi][ni][0]) * du[mi][ni][0],
                      silu_f(dg[mi][ni][1]) * du[mi][ni][1]);
            h32[(size_t)(r + 8) * (NM / 2) + cw] =
                pack2(silu_f(dg[mi][ni][2]) * du[mi][ni][2],
                      silu_f(dg[mi][ni][3]) * du[mi][ni][3]);
        }
}

// ---------------- GEMM2: out += h @ Wd, CTA 128m x 128n, 256 thr, warp 32m x 64n ----------
template <bool SHARED>
__global__ void __launch_bounds__(256, 2)
moe_gemm2_mma(const __half* __restrict__ Wd, float* __restrict__ out) {
    extern __shared__ uint32_t smw[];
    int by = blockIdx.y, e, base;
    if (SHARED) { e = 0; base = by * 128; }
    else {
        if (by >= g_num_tiles) return;
        e = g_tile_e[by];
        base = g_tile_base[by];
    }
    const int n0 = blockIdx.x * 128;
    const __half* wd = Wd + (size_t)e * NM * NH;
    const int hb = (SHARED ? SHARED_HBASE : 0) + base;

    const uint32_t sbase = smem_u32(smw);
    const int tid = threadIdx.x;
    const int lane = tid & 31, wid = tid >> 5;
    const int j = lane & 3, g = lane >> 2;
    const int wm = (wid & 3) * 32, wn = (wid >> 2) * 64;

    const int a_row  = wm + ((lane >> 3) & 1) * 8 + (lane & 7);
    const int a_coff = (lane >> 4) * 4;
    const int b_krow = ((lane >> 3) & 1) * 8 + (lane & 7);
    const int b_coff = (wn >> 1) + (lane >> 4) * 4;

    const int row_a = tid & 127, qa0 = (tid >> 7) * 2;
    const __half* ax = g_hbuf + (size_t)(hb + row_a) * NM + 8 * qa0;
    const int bkk = tid >> 3, bc0 = (tid & 7) * 2;
    const uint32_t a_dst = sbase + (row_a * A_W + 4 * qa0) * 4;
    const uint32_t b_dst = sbase + (A_BUFW + bkk * B_W + 4 * bc0) * 4;
    const __half* wdp = wd + (size_t)bkk * NH + n0 + 8 * bc0;

    float d[2][8][4];
#pragma unroll
    for (int a1 = 0; a1 < 2; a1++)
#pragma unroll
        for (int b1 = 0; b1 < 8; b1++)
#pragma unroll
            for (int c1 = 0; c1 < 4; c1++) d[a1][b1][c1] = 0.f;

    const int KC = NM / 32;
#pragma unroll
    for (int s = 0; s < 3; s++) {
        uint32_t so = s * SW2 * 4;
        cpa16(a_dst + so, ax + s * 32, 16);
        cpa16(a_dst + so + 16, ax + s * 32 + 8, 16);
        cpa16(b_dst + so, wdp + (size_t)s * 32 * NH, 16);
        cpa16(b_dst + so + 16, wdp + (size_t)s * 32 * NH + 8, 16);
        CP_COMMIT();
    }

    for (int kc = 0; kc < KC; kc++) {
        CP_WAIT2();
        __syncthreads();
        const int st = kc & 3;
        const uint32_t asb = sbase + (st * SW2) * 4;
        const uint32_t bsb = asb + A_BUFW * 4;
#pragma unroll
        for (int ks = 0; ks < 2; ks++) {
            uint32_t a[2][4];
#pragma unroll
            for (int mi = 0; mi < 2; mi++)
                ldsm4(a[mi], asb + ((a_row + mi * 16) * A_W + ks * 8 + a_coff) * 4);
            uint32_t fb[4][4];
#pragma unroll
            for (int nip = 0; nip < 4; nip++)
                ldsm4t(fb[nip], bsb + ((b_krow + ks * 16) * B_W + b_coff + nip * 8) * 4);
#pragma unroll
            for (int ni = 0; ni < 8; ni++) {
                int nip = ni >> 1, o = (ni & 1) * 2;
#pragma unroll
                for (int mi = 0; mi < 2; mi++)
                    mma16(d[mi][ni], a[mi], fb[nip][o], fb[nip][o + 1]);
            }
        }
        int nk = kc + 3;
        if (nk < KC) {
            uint32_t so = (nk & 3) * SW2 * 4;
            cpa16(a_dst + so, ax + nk * 32, 16);
            cpa16(a_dst + so + 16, ax + nk * 32 + 8, 16);
            cpa16(b_dst + so, wdp + (size_t)nk * 32 * NH, 16);
            cpa16(b_dst + so + 16, wdp + (size_t)nk * 32 * NH + 8, 16);
        }
        CP_COMMIT();
    }

    if (SHARED) {
#pragma unroll
        for (int mi = 0; mi < 2; mi++)
#pragma unroll
            for (int ni = 0; ni < 8; ni++) {
                int r = base + wm + 16 * mi + g;
                int col = n0 + wn + 8 * ni + 2 * j;
                *(float2*)(out + (size_t)r * NH + col) =
                    make_float2(d[mi][ni][0], d[mi][ni][1]);
                *(float2*)(out + (size_t)(r + 8) * NH + col) =
                    make_float2(d[mi][ni][2], d[mi][ni][3]);
            }
    } else {
#pragma unroll
        for (int mi = 0; mi < 2; mi++) {
            int s0 = base + wm + 16 * mi + g;
            int t0 = g_rows[s0], t1 = g_rows[s0 + 8];
            float w0 = g_wts[s0], w1 = g_wts[s0 + 8];
#pragma unroll
            for (int ni = 0; ni < 8; ni++) {
                int col = n0 + wn + 8 * ni + 2 * j;
                if (t0 >= 0) {
                    atomicAdd(out + (size_t)t0 * NH + col,     w0 * d[mi][ni][0]);
                    atomicAdd(out + (size_t)t0 * NH + col + 1, w0 * d[mi][ni][1]);
                }
                if (t1 >= 0) {
                    atomicAdd(out + (size_t)t1 * NH + col,     w1 * d[mi][ni][2]);
                    atomicAdd(out + (size_t)t1 * NH + col + 1, w1 * d[mi][ni][3]);
                }
            }
        }
    }
}

// ---------------- launch ----------------
extern "C" void kernel_launch(void* const* d_in, const int* in_sizes, int n_in,
                              void* d_out, int out_size) {
    const float* x    = (const float*)d_in[0];
    const float* gw   = (const float*)d_in[1];
    const float* beta = (const float*)d_in[2];
    const float* gpw  = (const float*)d_in[3];
    const float* upw  = (const float*)d_in[4];
    const float* dpw  = (const float*)d_in[5];
    const float* sgw  = (const float*)d_in[6];
    const float* suw  = (const float*)d_in[7];
    const float* sdw  = (const float*)d_in[8];
    float* out = (float*)d_out;

    static __half *wgh = nullptr, *wuh = nullptr, *wdh = nullptr,
                  *sgh = nullptr, *suh = nullptr, *sdh = nullptr, *xh = nullptr;
    static cudaStream_t s1 = nullptr;
    static cudaEvent_t ev_fork = nullptr, ev_build = nullptr, ev_g1r = nullptr;
    if (!wgh) {
        void* p;
        cudaGetSymbolAddress(&p, g_wgh); wgh = (__half*)p;
        cudaGetSymbolAddress(&p, g_wuh); wuh = (__half*)p;
        cudaGetSymbolAddress(&p, g_wdh); wdh = (__half*)p;
        cudaGetSymbolAddress(&p, g_sgh); sgh = (__half*)p;
        cudaGetSymbolAddress(&p, g_suh); suh = (__half*)p;
        cudaGetSymbolAddress(&p, g_sdh); sdh = (__half*)p;
        cudaGetSymbolAddress(&p, g_xh);  xh  = (__half*)p;
        cudaFuncSetAttribute(moe_gemm1_mma<false>, cudaFuncAttributeMaxDynamicSharedMemorySize, SMEM1_BYTES);
        cudaFuncSetAttribute(moe_gemm1_mma<true>,  cudaFuncAttributeMaxDynamicSharedMemorySize, SMEM1_BYTES);
        cudaFuncSetAttribute(moe_gemm2_mma<false>, cudaFuncAttributeMaxDynamicSharedMemorySize, SMEM2_BYTES);
        cudaFuncSetAttribute(moe_gemm2_mma<true>,  cudaFuncAttributeMaxDynamicSharedMemorySize, SMEM2_BYTES);
        cudaStreamCreateWithFlags(&s1, cudaStreamNonBlocking);
        cudaEventCreateWithFlags(&ev_fork, cudaEventDisableTiming);
        cudaEventCreateWithFlags(&ev_build, cudaEventDisableTiming);
        cudaEventCreateWithFlags(&ev_g1r, cudaEventDisableTiming);
    }

    const int NBIG16 = NE * NH * NM / 16;
    const int NSML16 = NH * NM / 16;

    // Fork: big expert-weight conversions on side stream s1.
    cudaEventRecord(ev_fork, 0);
    cudaStreamWaitEvent(s1, ev_fork, 0);
    cvt16x3<<<(3 * NBIG16 + 255) / 256, 256, 0, s1>>>(
        (const float4*)gpw, (const float4*)upw, (const float4*)dpw,
        (uint4*)wgh, (uint4*)wuh, (uint4*)wdh, NBIG16);

    // Main stream: small cvt + routing + build.
    cvt16x3<<<(3 * NSML16 + 255) / 256, 256>>>(
        (const float4*)sgw, (const float4*)suw, (const float4*)sdw,
        (uint4*)sgh, (uint4*)suh, (uint4*)sdh, NSML16);
    moe_route<<<NTOK, 256>>>(x, gw, beta);
    moe_build<<<1, 512>>>();
    cudaEventRecord(ev_build, 0);

    // Side stream: routed gemm1 (needs big cvt [in-stream] + build/xh [event]).
    cudaStreamWaitEvent(s1, ev_build, 0);
    moe_gemm1_mma<false><<<dim3(NM / 128, 40), 512, SMEM1_BYTES, s1>>>(xh, wgh, wuh);
    cudaEventRecord(ev_g1r, s1);

    // Main stream: shared-expert chain (out initialized by shared gemm2).
    moe_gemm1_mma<true><<<dim3(NM / 128, NTOK / 128), 512, SMEM1_BYTES>>>(xh, sgh, suh);
    moe_gemm2_mma<true><<<dim3(NH / 128, NTOK / 128), 256, SMEM2_BYTES>>>(sdh, out);

    // Join: routed gemm2 needs routed h + initialized out.
    cudaStreamWaitEvent(0, ev_g1r, 0);
    moe_gemm2_mma<false><<<dim3(NH / 128, 40), 256, SMEM2_BYTES>>>(wdh, out);
}